// round 1
// baseline (speedup 1.0000x reference)
#include <cuda_runtime.h>
#include <cstdint>

// ---------------- problem constants ----------------
#define BB 4
#define NN 6
#define DD 41
#define FH 16
#define FW 44
#define CC 64
#define NX 200
#define NY 200
#define NP (BB*NN*DD*FH*FW)        // 692736 points
#define PTS_PER_BN (DD*FH*FW)      // 28864
#define SPATIAL (NX*NY)            // 40000

// scratch accumulator, channel-last: (B, NX, NY, C)
__device__ __align__(16) float g_scratch[BB * SPATIAL * CC];
// per-(b,n) params: comb[9], invPostRots[9], post_trans[3], trans[3] = 24 floats
__device__ float g_params[BB * NN * 24];

// ---------------- 3x3 inverse (adjugate) ----------------
__device__ __forceinline__ void inv3(const float* m, float* o) {
    float a=m[0],b=m[1],c=m[2],d=m[3],e=m[4],f=m[5],g=m[6],h=m[7],i=m[8];
    float A  =  (e*i - f*h);
    float Bm = -(d*i - f*g);
    float Cm =  (d*h - e*g);
    float det = a*A + b*Bm + c*Cm;
    float inv = 1.0f / det;
    o[0] =  A*inv;
    o[1] = -(b*i - c*h)*inv;
    o[2] =  (b*f - c*e)*inv;
    o[3] =  Bm*inv;
    o[4] =  (a*i - c*g)*inv;
    o[5] = -(a*f - c*d)*inv;
    o[6] =  Cm*inv;
    o[7] = -(a*h - b*g)*inv;
    o[8] =  (a*e - b*d)*inv;
}

// ---------------- precompute per-(b,n) transforms ----------------
__global__ void precompute_kernel(const float* __restrict__ rots,
                                  const float* __restrict__ intrins,
                                  const float* __restrict__ post_rots,
                                  const float* __restrict__ trans,
                                  const float* __restrict__ post_trans) {
    int i = threadIdx.x;
    if (i >= BB*NN) return;
    const float* R  = rots      + i*9;
    const float* K  = intrins   + i*9;
    const float* PR = post_rots + i*9;

    float iK[9], iPR[9], comb[9];
    inv3(K, iK);
    inv3(PR, iPR);
    // comb = R @ iK
    #pragma unroll
    for (int r = 0; r < 3; r++)
        #pragma unroll
        for (int c = 0; c < 3; c++)
            comb[r*3+c] = R[r*3+0]*iK[0*3+c] + R[r*3+1]*iK[1*3+c] + R[r*3+2]*iK[2*3+c];

    float* o = g_params + i*24;
    #pragma unroll
    for (int k = 0; k < 9; k++) o[k]   = comb[k];
    #pragma unroll
    for (int k = 0; k < 9; k++) o[9+k] = iPR[k];
    o[18] = post_trans[i*3+0]; o[19] = post_trans[i*3+1]; o[20] = post_trans[i*3+2];
    o[21] = trans[i*3+0];      o[22] = trans[i*3+1];      o[23] = trans[i*3+2];
}

// ---------------- zero the scratch accumulator ----------------
__global__ void zero_kernel() {
    int idx = blockIdx.x * blockDim.x + threadIdx.x;   // float4 index
    float4 z = make_float4(0.f, 0.f, 0.f, 0.f);
    reinterpret_cast<float4*>(g_scratch)[idx] = z;
}

// ---------------- geometry + scatter-add ----------------
// 16 lanes per point; lane l handles channels [4l, 4l+4) as one float4 red-op.
__global__ void scatter_kernel(const float* __restrict__ x) {
    int gtid = blockIdx.x * blockDim.x + threadIdx.x;
    int p    = gtid >> 4;          // point index
    int lane = gtid & 15;
    if (p >= NP) return;

    int bn  = p / PTS_PER_BN;
    int rem = p - bn * PTS_PER_BN;
    int d   = rem / (FH*FW);
    int hw  = rem - d * (FH*FW);
    int h   = hw / FW;
    int w   = hw - h * FW;
    int b   = bn / NN;

    const float* prm = g_params + bn*24;

    // frustum pixel coords (linspace over [0, OGW-1] / [0, OGH-1])
    float u   = (float)w * (351.0f / 43.0f);
    float v   = (float)h * (127.0f / 15.0f);
    float dep = 4.0f + (float)d;

    // p = frustum - post_trans
    float px = u   - prm[18];
    float py = v   - prm[19];
    float pz = dep - prm[20];
    // q = inv(post_rots) @ p
    float qx = prm[9]*px  + prm[10]*py + prm[11]*pz;
    float qy = prm[12]*px + prm[13]*py + prm[14]*pz;
    float qz = prm[15]*px + prm[16]*py + prm[17]*pz;
    // un-project: (u*z, v*z, z)
    float sx = qx * qz;
    float sy = qy * qz;
    float sz = qz;
    // geom = comb @ s + trans
    float gx = prm[0]*sx + prm[1]*sy + prm[2]*sz + prm[21];
    float gy = prm[3]*sx + prm[4]*sy + prm[5]*sz + prm[22];
    float gz = prm[6]*sx + prm[7]*sy + prm[8]*sz + prm[23];

    // voxel index: trunc-toward-zero like astype(int32)
    int ix = (int)((gx - (-50.0f)) / 0.5f);
    int iy = (int)((gy - (-50.0f)) / 0.5f);
    int iz = (int)((gz - (-10.0f)) / 20.0f);

    if (ix < 0 || ix >= NX || iy < 0 || iy >= NY || iz != 0) return;

    float4 val = reinterpret_cast<const float4*>(x + (size_t)p * CC)[lane];
    float* dst = g_scratch + ((size_t)(b*NX + ix)*NY + iy) * CC + lane*4;
    asm volatile("red.global.add.v4.f32 [%0], {%1, %2, %3, %4};"
                 :: "l"(dst), "f"(val.x), "f"(val.y), "f"(val.z), "f"(val.w)
                 : "memory");
}

// ---------------- transpose (B, S, C) -> (B, C, S) ----------------
__global__ void transpose_kernel(float* __restrict__ out) {
    __shared__ float tile[32][33];
    int b  = blockIdx.z;
    int c0 = blockIdx.y * 32;
    int s0 = blockIdx.x * 32;
    int tx = threadIdx.x;        // 0..31
    int ty = threadIdx.y;        // 0..7

    const float* src = g_scratch + (size_t)b * SPATIAL * CC;
    #pragma unroll
    for (int i = 0; i < 32; i += 8) {
        int s = s0 + ty + i;
        tile[ty + i][tx] = src[(size_t)s * CC + c0 + tx];
    }
    __syncthreads();
    float* dst = out + (size_t)b * CC * SPATIAL;
    #pragma unroll
    for (int i = 0; i < 32; i += 8) {
        int c = c0 + ty + i;
        dst[(size_t)c * SPATIAL + s0 + tx] = tile[tx][ty + i];
    }
}

// ---------------- launch ----------------
extern "C" void kernel_launch(void* const* d_in, const int* in_sizes, int n_in,
                              void* d_out, int out_size) {
    const float* x          = (const float*)d_in[0];
    const float* rots       = (const float*)d_in[1];
    const float* trans      = (const float*)d_in[2];
    const float* intrins    = (const float*)d_in[3];
    const float* post_rots  = (const float*)d_in[4];
    const float* post_trans = (const float*)d_in[5];
    float* out = (float*)d_out;

    precompute_kernel<<<1, 32>>>(rots, intrins, post_rots, trans, post_trans);

    // scratch = 10,240,000 floats = 2,560,000 float4
    zero_kernel<<<10000, 256>>>();

    // 16 lanes per point: 692736 * 16 = 11,083,776 threads / 256 = 43296 blocks
    scatter_kernel<<<43296, 256>>>(x);

    // S=40000 -> 1250 tiles of 32; C=64 -> 2 tiles; B=4
    transpose_kernel<<<dim3(1250, 2, 4), dim3(32, 8)>>>(out);
}